// round 1
// baseline (speedup 1.0000x reference)
#include <cuda_runtime.h>
#include <math.h>

#define Bn 8
#define Ln 8
#define Cn 64
#define Hn 56
#define Wn 56
#define HWn 3136
#define BCn (Bn*Cn)        // 512
#define BLn (Bn*Ln)        // 64
#define NTOT (BLn*Cn*HWn)  // 12,845,056

// ---------------- scratch (device globals; no runtime allocation) ----------
__device__ float2 g_F2[BCn*Ln*HWn];     // 2D-DFT result per (b,c,l) slab (~103MB)
__device__ float  g_y[NTOT];            // pre-BN conv output (~51MB)
__device__ float  g_ppart[BCn*7*Ln];    // pooled partials (deterministic reduce)
__device__ float  g_s[BLn*Cn];          // per (b,l,ci) input-channel scale
__device__ float  g_fb[BLn*Cn];         // per (b,l,co) dynamic bias
__device__ float  g_bnsum[Cn*BLn];
__device__ float  g_bnsq[Cn*BLn];
__device__ float  g_mean[Cn];
__device__ float  g_invstd[Cn];

// ============================================================================
// K1: per-(b,c,l) slab, 2D DFT (W then H) as two 56x56 register-tiled matmuls.
// blockIdx.x = bc*8 + l, 224 threads (196 active compute, 4x4 tiles).
// ============================================================================
__global__ __launch_bounds__(224) void k1_dft2d(const float* __restrict__ x) {
    __shared__ float  xs[HWn];        // 12.5 KB
    __shared__ float2 t1[HWn];        // 25 KB
    __shared__ float2 tw[56];

    int bid = blockIdx.x;             // bc*L + l
    int bc  = bid >> 3;
    int l   = bid & 7;
    int b   = bc >> 6;
    int c   = bc & 63;
    int tid = threadIdx.x;

    const float* xp = x + (size_t)((b*Ln + l)*Cn + c) * HWn;
    #pragma unroll
    for (int k = 0; k < 14; ++k) xs[tid + k*224] = xp[tid + k*224];

    if (tid < 56) {
        float sv, cv;
        sincosf(-6.28318530717958647692f * (float)tid / 56.0f, &sv, &cv);
        tw[tid] = make_float2(cv, sv);
    }
    __syncthreads();

    int th = tid / 14;                // 0..15 (14 valid)
    int tk = tid % 14;
    bool active = (th < 14);
    int h0  = th * 4;
    int kw0 = tk * 4;

    // ---- Stage B: W-DFT (real input). t1[h][kw] = sum_w xs[h][w]*tw[(w*kw)%56]
    if (active) {
        float2 acc[4][4];
        #pragma unroll
        for (int i = 0; i < 4; ++i)
            #pragma unroll
            for (int j = 0; j < 4; ++j) acc[i][j] = make_float2(0.f, 0.f);
        int idx[4] = {0, 0, 0, 0};
        for (int w = 0; w < 56; ++w) {
            float xa[4];
            #pragma unroll
            for (int i = 0; i < 4; ++i) xa[i] = xs[(h0 + i)*56 + w];
            #pragma unroll
            for (int j = 0; j < 4; ++j) {
                float2 t = tw[idx[j]];
                #pragma unroll
                for (int i = 0; i < 4; ++i) {
                    acc[i][j].x += xa[i] * t.x;
                    acc[i][j].y += xa[i] * t.y;
                }
                idx[j] += kw0 + j;
                if (idx[j] >= 56) idx[j] -= 56;
            }
        }
        #pragma unroll
        for (int i = 0; i < 4; ++i)
            #pragma unroll
            for (int j = 0; j < 4; ++j)
                t1[(h0 + i)*56 + kw0 + j] = acc[i][j];
    }
    __syncthreads();

    // ---- Stage C: H-DFT (complex). t2[kh][kw] = sum_h tw[(h*kh)%56]*t1[h][kw]
    if (active) {
        float2 acc[4][4];
        #pragma unroll
        for (int i = 0; i < 4; ++i)
            #pragma unroll
            for (int j = 0; j < 4; ++j) acc[i][j] = make_float2(0.f, 0.f);
        int idx[4] = {0, 0, 0, 0};     // (h*kh_i)%56, kh_i = h0+i
        for (int h = 0; h < 56; ++h) {
            float2 tv[4];
            #pragma unroll
            for (int i = 0; i < 4; ++i) {
                tv[i] = tw[idx[i]];
                idx[i] += h0 + i;
                if (idx[i] >= 56) idx[i] -= 56;
            }
            float2 u[4];
            #pragma unroll
            for (int j = 0; j < 4; ++j) u[j] = t1[h*56 + kw0 + j];
            #pragma unroll
            for (int i = 0; i < 4; ++i)
                #pragma unroll
                for (int j = 0; j < 4; ++j) {
                    acc[i][j].x += tv[i].x*u[j].x - tv[i].y*u[j].y;
                    acc[i][j].y += tv[i].x*u[j].y + tv[i].y*u[j].x;
                }
        }
        float2* outp = g_F2 + (size_t)bid * HWn;
        #pragma unroll
        for (int i = 0; i < 4; ++i)
            #pragma unroll
            for (int j = 0; j < 4; ++j)
                outp[(h0 + i)*56 + kw0 + j] = acc[i][j];
    }
}

// ============================================================================
// K2: 8-point DFT along L + magnitude + pooled partial reduction.
// grid = BC*7 blocks of 448 threads; each thread owns one (h,w) position.
// ============================================================================
__global__ __launch_bounds__(448) void k2_ldft(const float* __restrict__ x) {
    int bx = blockIdx.x;
    int bc = bx / 7, jb = bx % 7;
    int b  = bc >> 6, c = bc & 63;
    int tid = threadIdx.x;
    int p   = jb * 448 + tid;         // 0..3135

    const float2* f2 = g_F2 + (size_t)bc * Ln * HWn + p;
    float fr[8], fi[8];
    #pragma unroll
    for (int l2 = 0; l2 < 8; ++l2) {
        float2 v = f2[(size_t)l2 * HWn];
        fr[l2] = v.x; fi[l2] = v.y;
    }

    const float RT = 0.70710678118654752f;
    const float twc[8] = {1.f,  RT, 0.f, -RT, -1.f, -RT, 0.f,  RT};
    const float tws[8] = {0.f, -RT, -1.f, -RT, 0.f,  RT, 1.f,  RT};
    const float SCALE = 0.01f / 158.39507568359375f;   // 0.01/sqrt(8*56*56)

    float contrib[8];
    #pragma unroll
    for (int k = 0; k < 8; ++k) {
        float re = 0.f, im = 0.f;
        #pragma unroll
        for (int l2 = 0; l2 < 8; ++l2) {
            int j = (l2 * k) & 7;
            re += twc[j]*fr[l2] - tws[j]*fi[l2];
            im += twc[j]*fi[l2] + tws[j]*fr[l2];
        }
        float mag = sqrtf(re*re + im*im);
        float xv  = x[(size_t)((b*Ln + k)*Cn + c) * HWn + p];
        contrib[k] = xv * (1.0f + SCALE * mag);
    }

    // deterministic block reduce of 8 sums
    #pragma unroll
    for (int k = 0; k < 8; ++k)
        #pragma unroll
        for (int off = 16; off > 0; off >>= 1)
            contrib[k] += __shfl_down_sync(0xffffffff, contrib[k], off);

    __shared__ float ws[14][8];
    int wid = tid >> 5, lane = tid & 31;
    if (lane == 0) {
        #pragma unroll
        for (int k = 0; k < 8; ++k) ws[wid][k] = contrib[k];
    }
    __syncthreads();
    if (tid < 8) {
        float s = 0.f;
        #pragma unroll
        for (int w2 = 0; w2 < 14; ++w2) s += ws[w2][tid];
        g_ppart[(bc*7 + jb)*8 + tid] = s;
    }
}

// ============================================================================
// K3: pooled -> calibration scale s[b,l,ci] and dynamic bias fb[b,l,co].
// grid = 64 blocks (one per (b,l)), 64 threads.
// ============================================================================
__global__ __launch_bounds__(64) void k3_calib(
    const float* __restrict__ tw_, const float* __restrict__ tb,
    const float* __restrict__ fcw, const float* __restrict__ fcb,
    const float* __restrict__ convb)
{
    int bl = blockIdx.x;
    int b  = bl >> 3, l = bl & 7;
    int tid = threadIdx.x;

    __shared__ float pooled[64];
    __shared__ float fcp[65];

    float s = 0.f;
    #pragma unroll
    for (int j = 0; j < 7; ++j)
        s += g_ppart[((b*Cn + tid)*7 + j)*8 + l];
    float pv = s * (1.0f / 3136.0f);
    pooled[tid] = pv;
    fcp[tid] = fcw[tid] * pv;
    __syncthreads();

    float calib = tb[tid];
    #pragma unroll 8
    for (int c = 0; c < 64; ++c) calib += tw_[tid*64 + c] * pooled[c];
    g_s[bl*Cn + tid] = calib + 1.0f;

    if (tid == 0) {
        float f = fcb[0];
        for (int c = 0; c < 64; ++c) f += fcp[c];
        fcp[64] = f + 1.0f;
    }
    __syncthreads();
    g_fb[bl*Cn + tid] = convb[tid] * fcp[64];
}

// ============================================================================
// K4: conv3x3 with s folded into weights + dyn bias + residual + BN partials.
// grid = (16 co-groups, 64 bl), 448 threads; thread tile = 7 rows x 4 co.
// ============================================================================
__global__ __launch_bounds__(448) void k4_conv(const float* __restrict__ x,
                                               const float* __restrict__ convw) {
    __shared__ float xt[58*58];       // 13.4 KB, halo-padded tile
    __shared__ float wsm[64*9*4];     // 9.2 KB: [ci][tap][cg]
    __shared__ float ssh[64];
    __shared__ float red[14*8];

    int cog = blockIdx.x;             // 0..15
    int bl  = blockIdx.y;             // 0..63
    int co0 = cog * 4;
    int tid = threadIdx.x;

    if (tid < 64) ssh[tid] = g_s[bl*Cn + tid];
    for (int e = tid; e < 58*58; e += 448) xt[e] = 0.0f;
    __syncthreads();

    for (int e = tid; e < 2304; e += 448) {
        int ci = e / 36; int r = e % 36; int tap = r >> 2; int cg = r & 3;
        wsm[e] = convw[((co0 + cg)*64 + ci)*9 + tap] * ssh[ci];
    }

    int wc = tid % 56;
    int hq = tid / 56;                // 0..7
    int h0 = hq * 7;

    float acc[7][4];
    #pragma unroll
    for (int r = 0; r < 7; ++r)
        #pragma unroll
        for (int g = 0; g < 4; ++g) acc[r][g] = 0.f;

    const float* xb = x + (size_t)bl * Cn * HWn;
    __syncthreads();

    for (int ci = 0; ci < 64; ++ci) {
        const float* xp = xb + (size_t)ci * HWn;
        #pragma unroll
        for (int k = 0; k < 7; ++k) {
            int e  = tid + k*448;
            int hh = e / 56, ww2 = e % 56;
            xt[(hh + 1)*58 + ww2 + 1] = xp[e];
        }
        __syncthreads();

        float a[9][3];
        #pragma unroll
        for (int j = 0; j < 9; ++j)
            #pragma unroll
            for (int d = 0; d < 3; ++d)
                a[j][d] = xt[(h0 + j)*58 + wc + d];

        #pragma unroll
        for (int tap = 0; tap < 9; ++tap) {
            float4 wv = *(const float4*)&wsm[(ci*9 + tap)*4];
            int dr = tap / 3, dc = tap % 3;
            #pragma unroll
            for (int r = 0; r < 7; ++r) {
                float xv = a[r + dr][dc];
                acc[r][0] += wv.x * xv;
                acc[r][1] += wv.y * xv;
                acc[r][2] += wv.z * xv;
                acc[r][3] += wv.w * xv;
            }
        }
        __syncthreads();
    }

    // epilogue: + fb + residual, write y, accumulate BN partials
    float psum[4] = {0,0,0,0}, psq[4] = {0,0,0,0};
    #pragma unroll
    for (int cg = 0; cg < 4; ++cg) {
        int co = co0 + cg;
        float fbv = g_fb[bl*Cn + co];
        const float* xr = xb + (size_t)co * HWn;
        float* yp = g_y + (size_t)(bl*Cn + co) * HWn;
        #pragma unroll
        for (int r = 0; r < 7; ++r) {
            int pp = (h0 + r)*56 + wc;
            float v = acc[r][cg] + fbv + xr[pp];
            yp[pp] = v;
            psum[cg] += v;
            psq[cg]  += v*v;
        }
    }
    #pragma unroll
    for (int cg = 0; cg < 4; ++cg)
        #pragma unroll
        for (int off = 16; off > 0; off >>= 1) {
            psum[cg] += __shfl_down_sync(0xffffffff, psum[cg], off);
            psq[cg]  += __shfl_down_sync(0xffffffff, psq[cg],  off);
        }
    int wid = tid >> 5, lane = tid & 31;
    if (lane == 0) {
        #pragma unroll
        for (int cg = 0; cg < 4; ++cg) {
            red[wid*8 + cg]     = psum[cg];
            red[wid*8 + 4 + cg] = psq[cg];
        }
    }
    __syncthreads();
    if (tid < 8) {
        float s = 0.f;
        #pragma unroll
        for (int w2 = 0; w2 < 14; ++w2) s += red[w2*8 + tid];
        if (tid < 4) g_bnsum[(co0 + tid)*64 + bl]     = s;
        else         g_bnsq [(co0 + tid - 4)*64 + bl] = s;
    }
}

// ============================================================================
// K4b: final BN statistics (1 block, 64 threads; deterministic)
// ============================================================================
__global__ __launch_bounds__(64) void k4b_stats() {
    int c = threadIdx.x;
    float s = 0.f, q = 0.f;
    #pragma unroll 8
    for (int j = 0; j < 64; ++j) { s += g_bnsum[c*64 + j]; q += g_bnsq[c*64 + j]; }
    const float invN = 1.0f / (float)(BLn * HWn);
    float mean = s * invN;
    float var  = q * invN - mean*mean;
    g_mean[c]   = mean;
    g_invstd[c] = rsqrtf(var + 1e-5f);
}

// ============================================================================
// K5: BN normalize + affine + SiLU -> d_out
// ============================================================================
__global__ __launch_bounds__(256) void k5_bnsilu(const float* __restrict__ gamma,
                                                 const float* __restrict__ beta,
                                                 float* __restrict__ out) {
    int i = blockIdx.x * 256 + threadIdx.x;
    int c = (i / HWn) & 63;
    float v = (g_y[i] - g_mean[c]) * g_invstd[c] * gamma[c] + beta[c];
    out[i] = v / (1.0f + expf(-v));
}

// ============================================================================
extern "C" void kernel_launch(void* const* d_in, const int* in_sizes, int n_in,
                              void* d_out, int out_size) {
    const float* x          = (const float*)d_in[0];
    const float* temporal_w = (const float*)d_in[1];
    const float* temporal_b = (const float*)d_in[2];
    const float* fc_w       = (const float*)d_in[3];
    const float* fc_b       = (const float*)d_in[4];
    const float* conv_w     = (const float*)d_in[5];
    const float* conv_b     = (const float*)d_in[6];
    const float* bn_gamma   = (const float*)d_in[7];
    const float* bn_beta    = (const float*)d_in[8];
    float* out = (float*)d_out;

    k1_dft2d<<<BCn*Ln, 224>>>(x);                 // 4096 blocks
    k2_ldft<<<BCn*7, 448>>>(x);                   // 3584 blocks
    k3_calib<<<BLn, 64>>>(temporal_w, temporal_b, fc_w, fc_b, conv_b);
    k4_conv<<<dim3(16, BLn), 448>>>(x, conv_w);   // 1024 blocks
    k4b_stats<<<1, 64>>>();
    k5_bnsilu<<<NTOT/256, 256>>>(bn_gamma, bn_beta, out);
}

// round 2
// speedup vs baseline: 1.2375x; 1.2375x over previous
#include <cuda_runtime.h>
#include <math.h>

#define Bn 8
#define Ln 8
#define Cn 64
#define Hn 56
#define Wn 56
#define HWn 3136
#define BCn (Bn*Cn)        // 512
#define BLn (Bn*Ln)        // 64
#define NTOT (BLn*Cn*HWn)  // 12,845,056

// ---------------- scratch (device globals; no runtime allocation) ----------
__device__ float2 g_F2[BCn*Ln*HWn];     // 2D-DFT result per (b,c,l) slab (~103MB)
__device__ float  g_y[NTOT];            // pre-BN conv output (~51MB)
__device__ float  g_ppart[BCn*7*Ln];    // pooled partials (deterministic reduce)
__device__ float  g_s[BLn*Cn];          // per (b,l,ci) input-channel scale
__device__ float  g_fb[BLn*Cn];         // per (b,l,co) dynamic bias
__device__ float  g_bnsum[Cn*BLn];
__device__ float  g_bnsq[Cn*BLn];
__device__ float  g_mean[Cn];
__device__ float  g_invstd[Cn];

// ============================================================================
// K1: per-(b,c,l) slab 2D DFT, exploiting Hermitian symmetry of the real
// input: only kw in [0,31] computed (columns 0..28 stored directly, columns
// 29..55 filled as conjugate mirrors of 27..1). Padded smem (pitch 57 / 33)
// for conflict-free LDS. 112 compute threads per block, 4x4 register tiles.
// ============================================================================
__global__ __launch_bounds__(224) void k1_dft2d(const float* __restrict__ x) {
    __shared__ float  xs[56*57];      // padded rows: bank-conflict-free
    __shared__ float2 t1[56*33];      // only kw 0..31 needed; odd pitch
    __shared__ float2 tw[56];

    int bid = blockIdx.x;             // bc*L + l
    int bc  = bid >> 3;
    int l   = bid & 7;
    int b   = bc >> 6;
    int c   = bc & 63;
    int tid = threadIdx.x;

    const float* xp = x + (size_t)((b*Ln + l)*Cn + c) * HWn;
    #pragma unroll
    for (int k = 0; k < 14; ++k) {
        int e = tid + k*224;
        xs[(e/56)*57 + (e%56)] = xp[e];
    }
    if (tid < 56) {
        float sv, cv;
        sincosf(-6.28318530717958647692f * (float)tid / 56.0f, &sv, &cv);
        tw[tid] = make_float2(cv, sv);
    }
    __syncthreads();

    int th = tid >> 3;                // 0..27 (need 0..13)
    int tk = tid & 7;                 // 0..7
    bool active = (tid < 112);
    int h0  = th * 4;
    int kw0 = tk * 4;                 // kw in [0,32)

    // ---- Stage B: W-DFT (real input) for kw in [0,32)
    if (active) {
        float2 acc[4][4];
        #pragma unroll
        for (int i = 0; i < 4; ++i)
            #pragma unroll
            for (int j = 0; j < 4; ++j) acc[i][j] = make_float2(0.f, 0.f);
        int idx[4] = {0, 0, 0, 0};
        for (int w = 0; w < 56; ++w) {
            float xa[4];
            #pragma unroll
            for (int i = 0; i < 4; ++i) xa[i] = xs[(h0 + i)*57 + w];
            #pragma unroll
            for (int j = 0; j < 4; ++j) {
                float2 t = tw[idx[j]];
                #pragma unroll
                for (int i = 0; i < 4; ++i) {
                    acc[i][j].x += xa[i] * t.x;
                    acc[i][j].y += xa[i] * t.y;
                }
                idx[j] += kw0 + j;
                if (idx[j] >= 56) idx[j] -= 56;
            }
        }
        #pragma unroll
        for (int i = 0; i < 4; ++i)
            #pragma unroll
            for (int j = 0; j < 4; ++j)
                t1[(h0 + i)*33 + kw0 + j] = acc[i][j];
    }
    __syncthreads();

    // ---- Stage C: H-DFT (complex) for all kh, kw in [0,32); mirror-write rest
    if (active) {
        float2 acc[4][4];
        #pragma unroll
        for (int i = 0; i < 4; ++i)
            #pragma unroll
            for (int j = 0; j < 4; ++j) acc[i][j] = make_float2(0.f, 0.f);
        int idx[4] = {0, 0, 0, 0};     // (h*kh_i)%56, kh_i = h0+i
        for (int h = 0; h < 56; ++h) {
            float2 tv[4];
            #pragma unroll
            for (int i = 0; i < 4; ++i) {
                tv[i] = tw[idx[i]];
                idx[i] += h0 + i;
                if (idx[i] >= 56) idx[i] -= 56;
            }
            float2 u[4];
            #pragma unroll
            for (int j = 0; j < 4; ++j) u[j] = t1[h*33 + kw0 + j];
            #pragma unroll
            for (int i = 0; i < 4; ++i)
                #pragma unroll
                for (int j = 0; j < 4; ++j) {
                    acc[i][j].x += tv[i].x*u[j].x - tv[i].y*u[j].y;
                    acc[i][j].y += tv[i].x*u[j].y + tv[i].y*u[j].x;
                }
        }
        float2* outp = g_F2 + (size_t)bid * HWn;
        #pragma unroll
        for (int i = 0; i < 4; ++i) {
            int kh  = h0 + i;
            int mkh = (56 - kh) % 56;
            #pragma unroll
            for (int j = 0; j < 4; ++j) {
                int kw = kw0 + j;
                if (kw <= 28)
                    outp[kh*56 + kw] = acc[i][j];
                if (kw >= 1 && kw <= 27)
                    outp[mkh*56 + (56 - kw)] = make_float2(acc[i][j].x, -acc[i][j].y);
            }
        }
    }
}

// ============================================================================
// K2: 8-point DFT along L + magnitude + pooled partial reduction.
// grid = BC*7 blocks of 448 threads; each thread owns one (h,w) position.
// ============================================================================
__global__ __launch_bounds__(448) void k2_ldft(const float* __restrict__ x) {
    int bx = blockIdx.x;
    int bc = bx / 7, jb = bx % 7;
    int b  = bc >> 6, c = bc & 63;
    int tid = threadIdx.x;
    int p   = jb * 448 + tid;         // 0..3135

    const float2* f2 = g_F2 + (size_t)bc * Ln * HWn + p;
    float fr[8], fi[8];
    #pragma unroll
    for (int l2 = 0; l2 < 8; ++l2) {
        float2 v = f2[(size_t)l2 * HWn];
        fr[l2] = v.x; fi[l2] = v.y;
    }

    const float RT = 0.70710678118654752f;
    const float twc[8] = {1.f,  RT, 0.f, -RT, -1.f, -RT, 0.f,  RT};
    const float tws[8] = {0.f, -RT, -1.f, -RT, 0.f,  RT, 1.f,  RT};
    const float SCALE = 0.01f / 158.39507568359375f;   // 0.01/sqrt(8*56*56)

    float contrib[8];
    #pragma unroll
    for (int k = 0; k < 8; ++k) {
        float re = 0.f, im = 0.f;
        #pragma unroll
        for (int l2 = 0; l2 < 8; ++l2) {
            int j = (l2 * k) & 7;
            re += twc[j]*fr[l2] - tws[j]*fi[l2];
            im += twc[j]*fi[l2] + tws[j]*fr[l2];
        }
        float mag = sqrtf(re*re + im*im);
        float xv  = x[(size_t)((b*Ln + k)*Cn + c) * HWn + p];
        contrib[k] = xv * (1.0f + SCALE * mag);
    }

    #pragma unroll
    for (int k = 0; k < 8; ++k)
        #pragma unroll
        for (int off = 16; off > 0; off >>= 1)
            contrib[k] += __shfl_down_sync(0xffffffff, contrib[k], off);

    __shared__ float ws[14][8];
    int wid = tid >> 5, lane = tid & 31;
    if (lane == 0) {
        #pragma unroll
        for (int k = 0; k < 8; ++k) ws[wid][k] = contrib[k];
    }
    __syncthreads();
    if (tid < 8) {
        float s = 0.f;
        #pragma unroll
        for (int w2 = 0; w2 < 14; ++w2) s += ws[w2][tid];
        g_ppart[(bc*7 + jb)*8 + tid] = s;
    }
}

// ============================================================================
// K3: pooled -> calibration scale s[b,l,ci] and dynamic bias fb[b,l,co].
// ============================================================================
__global__ __launch_bounds__(64) void k3_calib(
    const float* __restrict__ tw_, const float* __restrict__ tb,
    const float* __restrict__ fcw, const float* __restrict__ fcb,
    const float* __restrict__ convb)
{
    int bl = blockIdx.x;
    int b  = bl >> 3, l = bl & 7;
    int tid = threadIdx.x;

    __shared__ float pooled[64];
    __shared__ float fcp[65];

    float s = 0.f;
    #pragma unroll
    for (int j = 0; j < 7; ++j)
        s += g_ppart[((b*Cn + tid)*7 + j)*8 + l];
    float pv = s * (1.0f / 3136.0f);
    pooled[tid] = pv;
    fcp[tid] = fcw[tid] * pv;
    __syncthreads();

    float calib = tb[tid];
    #pragma unroll 8
    for (int c = 0; c < 64; ++c) calib += tw_[tid*64 + c] * pooled[c];
    g_s[bl*Cn + tid] = calib + 1.0f;

    if (tid == 0) {
        float f = fcb[0];
        for (int c = 0; c < 64; ++c) f += fcp[c];
        fcp[64] = f + 1.0f;
    }
    __syncthreads();
    g_fb[bl*Cn + tid] = convb[tid] * fcp[64];
}

// ============================================================================
// K4: conv3x3, s folded into weights; double-buffered x tile with register
// prefetch so the global load overlaps the 252 FMAs; ONE barrier per ci.
// grid = (16 co-groups, 64 bl), 448 threads; thread tile = 7 rows x 4 co.
// ============================================================================
__global__ __launch_bounds__(448, 2) void k4_conv(const float* __restrict__ x,
                                                  const float* __restrict__ convw) {
    __shared__ float xt[2*58*58];     // 26.9 KB, halo-padded double buffer
    __shared__ float wsm[64*9*4];     // 9.2 KB: [ci][tap][cg]
    __shared__ float ssh[64];
    __shared__ float red[14*8];

    int cog = blockIdx.x;             // 0..15
    int bl  = blockIdx.y;             // 0..63
    int co0 = cog * 4;
    int tid = threadIdx.x;

    if (tid < 64) ssh[tid] = g_s[bl*Cn + tid];
    for (int e = tid; e < 2*58*58; e += 448) xt[e] = 0.0f;
    __syncthreads();

    for (int e = tid; e < 2304; e += 448) {
        int ci = e / 36; int r = e % 36; int tap = r >> 2; int cg = r & 3;
        wsm[e] = convw[((co0 + cg)*64 + ci)*9 + tap] * ssh[ci];
    }

    const float* xb = x + (size_t)bl * Cn * HWn;

    // preload ci = 0 into buffer 0
    #pragma unroll
    for (int k = 0; k < 7; ++k) {
        int e  = tid + k*448;
        int hh = e / 56, ww2 = e % 56;
        xt[(hh + 1)*58 + ww2 + 1] = __ldg(xb + e);
    }
    __syncthreads();

    int wc = tid % 56;
    int hq = tid / 56;                // 0..7
    int h0 = hq * 7;

    float acc[7][4];
    #pragma unroll
    for (int r = 0; r < 7; ++r)
        #pragma unroll
        for (int g = 0; g < 4; ++g) acc[r][g] = 0.f;

    for (int ci = 0; ci < 64; ++ci) {
        // issue next tile's global loads first (hidden behind the FMAs)
        float v[7];
        if (ci < 63) {
            const float* xp = xb + (size_t)(ci + 1) * HWn;
            #pragma unroll
            for (int k = 0; k < 7; ++k) v[k] = __ldg(xp + tid + k*448);
        }

        const float* xc = xt + (ci & 1) * (58*58);
        #pragma unroll
        for (int dc = 0; dc < 3; ++dc) {
            float a[9];
            #pragma unroll
            for (int j = 0; j < 9; ++j) a[j] = xc[(h0 + j)*58 + wc + dc];
            #pragma unroll
            for (int dr = 0; dr < 3; ++dr) {
                float4 wv = *(const float4*)&wsm[(ci*9 + dr*3 + dc)*4];
                #pragma unroll
                for (int r = 0; r < 7; ++r) {
                    float xv = a[r + dr];
                    acc[r][0] += wv.x * xv;
                    acc[r][1] += wv.y * xv;
                    acc[r][2] += wv.z * xv;
                    acc[r][3] += wv.w * xv;
                }
            }
        }

        if (ci < 63) {
            float* xn = xt + ((ci + 1) & 1) * (58*58);
            #pragma unroll
            for (int k = 0; k < 7; ++k) {
                int e  = tid + k*448;
                int hh = e / 56, ww2 = e % 56;
                xn[(hh + 1)*58 + ww2 + 1] = v[k];
            }
        }
        __syncthreads();
    }

    // epilogue: + fb + residual, write y, accumulate BN partials
    float psum[4] = {0,0,0,0}, psq[4] = {0,0,0,0};
    #pragma unroll
    for (int cg = 0; cg < 4; ++cg) {
        int co = co0 + cg;
        float fbv = g_fb[bl*Cn + co];
        const float* xr = xb + (size_t)co * HWn;
        float* yp = g_y + (size_t)(bl*Cn + co) * HWn;
        #pragma unroll
        for (int r = 0; r < 7; ++r) {
            int pp = (h0 + r)*56 + wc;
            float v = acc[r][cg] + fbv + xr[pp];
            yp[pp] = v;
            psum[cg] += v;
            psq[cg]  += v*v;
        }
    }
    #pragma unroll
    for (int cg = 0; cg < 4; ++cg)
        #pragma unroll
        for (int off = 16; off > 0; off >>= 1) {
            psum[cg] += __shfl_down_sync(0xffffffff, psum[cg], off);
            psq[cg]  += __shfl_down_sync(0xffffffff, psq[cg],  off);
        }
    int wid = tid >> 5, lane = tid & 31;
    if (lane == 0) {
        #pragma unroll
        for (int cg = 0; cg < 4; ++cg) {
            red[wid*8 + cg]     = psum[cg];
            red[wid*8 + 4 + cg] = psq[cg];
        }
    }
    __syncthreads();
    if (tid < 8) {
        float s = 0.f;
        #pragma unroll
        for (int w2 = 0; w2 < 14; ++w2) s += red[w2*8 + tid];
        if (tid < 4) g_bnsum[(co0 + tid)*64 + bl]     = s;
        else         g_bnsq [(co0 + tid - 4)*64 + bl] = s;
    }
}

// ============================================================================
// K4b: final BN statistics (1 block, 64 threads; deterministic)
// ============================================================================
__global__ __launch_bounds__(64) void k4b_stats() {
    int c = threadIdx.x;
    float s = 0.f, q = 0.f;
    #pragma unroll 8
    for (int j = 0; j < 64; ++j) { s += g_bnsum[c*64 + j]; q += g_bnsq[c*64 + j]; }
    const float invN = 1.0f / (float)(BLn * HWn);
    float mean = s * invN;
    float var  = q * invN - mean*mean;
    g_mean[c]   = mean;
    g_invstd[c] = rsqrtf(var + 1e-5f);
}

// ============================================================================
// K5: BN normalize + affine + SiLU -> d_out
// ============================================================================
__global__ __launch_bounds__(256) void k5_bnsilu(const float* __restrict__ gamma,
                                                 const float* __restrict__ beta,
                                                 float* __restrict__ out) {
    int i = blockIdx.x * 256 + threadIdx.x;
    int c = (i / HWn) & 63;
    float v = (g_y[i] - g_mean[c]) * g_invstd[c] * gamma[c] + beta[c];
    out[i] = v / (1.0f + expf(-v));
}

// ============================================================================
extern "C" void kernel_launch(void* const* d_in, const int* in_sizes, int n_in,
                              void* d_out, int out_size) {
    const float* x          = (const float*)d_in[0];
    const float* temporal_w = (const float*)d_in[1];
    const float* temporal_b = (const float*)d_in[2];
    const float* fc_w       = (const float*)d_in[3];
    const float* fc_b       = (const float*)d_in[4];
    const float* conv_w     = (const float*)d_in[5];
    const float* conv_b     = (const float*)d_in[6];
    const float* bn_gamma   = (const float*)d_in[7];
    const float* bn_beta    = (const float*)d_in[8];
    float* out = (float*)d_out;

    k1_dft2d<<<BCn*Ln, 224>>>(x);                 // 4096 blocks
    k2_ldft<<<BCn*7, 448>>>(x);                   // 3584 blocks
    k3_calib<<<BLn, 64>>>(temporal_w, temporal_b, fc_w, fc_b, conv_b);
    k4_conv<<<dim3(16, BLn), 448>>>(x, conv_w);   // 1024 blocks
    k4b_stats<<<1, 64>>>();
    k5_bnsilu<<<NTOT/256, 256>>>(bn_gamma, bn_beta, out);
}

// round 3
// speedup vs baseline: 1.3059x; 1.0552x over previous
#include <cuda_runtime.h>
#include <math.h>

#define Bn 8
#define Ln 8
#define Cn 64
#define Hn 56
#define Wn 56
#define HWn 3136
#define BCn (Bn*Cn)        // 512
#define BLn (Bn*Ln)        // 64
#define NTOT (BLn*Cn*HWn)  // 12,845,056

typedef unsigned long long u64;

__device__ __forceinline__ u64 ffma2(u64 a, u64 b, u64 c) {
    u64 d;
    asm("fma.rn.f32x2 %0, %1, %2, %3;" : "=l"(d) : "l"(a), "l"(b), "l"(c));
    return d;
}
__device__ __forceinline__ u64 pack2(float lo, float hi) {
    u64 d;
    asm("mov.b64 %0, {%1, %2};" : "=l"(d) : "f"(lo), "f"(hi));
    return d;
}
__device__ __forceinline__ float2 unpack2(u64 v) {
    float2 r;
    asm("mov.b64 {%0, %1}, %2;" : "=f"(r.x), "=f"(r.y) : "l"(v));
    return r;
}

// ---------------- scratch (device globals; no runtime allocation) ----------
__device__ float2 g_F2[BCn*Ln*HWn];     // 2D-DFT result per (b,c,l) slab (~103MB)
__device__ float  g_y[NTOT];            // pre-BN conv output (~51MB)
__device__ float  g_ppart[BCn*7*Ln];    // pooled partials (deterministic reduce)
__device__ float  g_s[BLn*Cn];          // per (b,l,ci) input-channel scale
__device__ float  g_fb[BLn*Cn];         // per (b,l,co) dynamic bias
__device__ float  g_bnsum[Cn*BLn];
__device__ float  g_bnsq[Cn*BLn];
__device__ float  g_mean[Cn];
__device__ float  g_invstd[Cn];

// ============================================================================
// K1: per-(b,c,l) slab 2D DFT with Hermitian symmetry (kw in [0,31]) and
// packed f32x2 complex MACs: acc += (c,c)*(re,im) + (-s,s)*(im,re).
// All packed operands live in smem -> broadcast LDS.64, zero packing ALU.
// ============================================================================
__global__ __launch_bounds__(224) void k1_dft2d(const float* __restrict__ x) {
    __shared__ float xs[56*57];                 // 12.8 KB padded
    __shared__ __align__(16) u64 t1a[56*33];    // (re,im)
    __shared__ __align__(16) u64 t1s[56*33];    // (im,re)
    __shared__ u64 twp[56];                     // (c, s)
    __shared__ u64 twA[56];                     // (c, c)
    __shared__ u64 twB[56];                     // (-s, s)

    int bid = blockIdx.x;             // bc*L + l
    int bc  = bid >> 3;
    int l   = bid & 7;
    int b   = bc >> 6;
    int c   = bc & 63;
    int tid = threadIdx.x;

    const float* xp = x + (size_t)((b*Ln + l)*Cn + c) * HWn;
    #pragma unroll
    for (int k = 0; k < 14; ++k) {
        int e = tid + k*224;
        xs[(e/56)*57 + (e%56)] = xp[e];
    }
    if (tid < 56) {
        float sv, cv;
        sincosf(-6.28318530717958647692f * (float)tid / 56.0f, &sv, &cv);
        twp[tid] = pack2(cv, sv);
        twA[tid] = pack2(cv, cv);
        twB[tid] = pack2(-sv, sv);
    }
    __syncthreads();

    int th = tid >> 3;                // 0..27 (need 0..13)
    int tk = tid & 7;                 // 0..7
    bool active = (tid < 112);
    int h0  = th * 4;
    int kw0 = tk * 4;                 // kw in [0,32)

    // ---- Stage B: W-DFT (real input) for kw in [0,32)
    if (active) {
        u64 acc2[4][4];
        #pragma unroll
        for (int i = 0; i < 4; ++i)
            #pragma unroll
            for (int j = 0; j < 4; ++j) acc2[i][j] = 0ull;
        int idx[4] = {0, 0, 0, 0};
        for (int w = 0; w < 56; ++w) {
            u64 xa2[4];
            #pragma unroll
            for (int i = 0; i < 4; ++i) {
                float v = xs[(h0 + i)*57 + w];
                xa2[i] = pack2(v, v);
            }
            #pragma unroll
            for (int j = 0; j < 4; ++j) {
                u64 t = twp[idx[j]];
                #pragma unroll
                for (int i = 0; i < 4; ++i)
                    acc2[i][j] = ffma2(xa2[i], t, acc2[i][j]);
                idx[j] += kw0 + j;
                if (idx[j] >= 56) idx[j] -= 56;
            }
        }
        #pragma unroll
        for (int i = 0; i < 4; ++i)
            #pragma unroll
            for (int j = 0; j < 4; ++j) {
                int o = (h0 + i)*33 + kw0 + j;
                t1a[o] = acc2[i][j];
                float2 v = unpack2(acc2[i][j]);
                t1s[o] = pack2(v.y, v.x);
            }
    }
    __syncthreads();

    // ---- Stage C: H-DFT (complex) for all kh, kw in [0,32); mirror-write rest
    if (active) {
        u64 acc2[4][4];
        #pragma unroll
        for (int i = 0; i < 4; ++i)
            #pragma unroll
            for (int j = 0; j < 4; ++j) acc2[i][j] = 0ull;
        int idx[4] = {0, 0, 0, 0};     // (h*kh_i)%56, kh_i = h0+i
        for (int h = 0; h < 56; ++h) {
            u64 tA[4], tB[4];
            #pragma unroll
            for (int i = 0; i < 4; ++i) {
                tA[i] = twA[idx[i]];
                tB[i] = twB[idx[i]];
                idx[i] += h0 + i;
                if (idx[i] >= 56) idx[i] -= 56;
            }
            u64 ua[4], us[4];
            #pragma unroll
            for (int j = 0; j < 4; ++j) {
                ua[j] = t1a[h*33 + kw0 + j];
                us[j] = t1s[h*33 + kw0 + j];
            }
            #pragma unroll
            for (int i = 0; i < 4; ++i)
                #pragma unroll
                for (int j = 0; j < 4; ++j) {
                    acc2[i][j] = ffma2(tA[i], ua[j], acc2[i][j]);
                    acc2[i][j] = ffma2(tB[i], us[j], acc2[i][j]);
                }
        }
        float2* outp = g_F2 + (size_t)bid * HWn;
        #pragma unroll
        for (int i = 0; i < 4; ++i) {
            int kh  = h0 + i;
            int mkh = (56 - kh) % 56;
            #pragma unroll
            for (int j = 0; j < 4; ++j) {
                int kw = kw0 + j;
                float2 v = unpack2(acc2[i][j]);
                if (kw <= 28)
                    outp[kh*56 + kw] = v;
                if (kw >= 1 && kw <= 27)
                    outp[mkh*56 + (56 - kw)] = make_float2(v.x, -v.y);
            }
        }
    }
}

// ============================================================================
// K2: 8-point DFT along L + magnitude + pooled partial reduction.
// ============================================================================
__global__ __launch_bounds__(448) void k2_ldft(const float* __restrict__ x) {
    int bx = blockIdx.x;
    int bc = bx / 7, jb = bx % 7;
    int b  = bc >> 6, c = bc & 63;
    int tid = threadIdx.x;
    int p   = jb * 448 + tid;         // 0..3135

    const float2* f2 = g_F2 + (size_t)bc * Ln * HWn + p;
    float fr[8], fi[8];
    #pragma unroll
    for (int l2 = 0; l2 < 8; ++l2) {
        float2 v = f2[(size_t)l2 * HWn];
        fr[l2] = v.x; fi[l2] = v.y;
    }

    const float RT = 0.70710678118654752f;
    const float twc[8] = {1.f,  RT, 0.f, -RT, -1.f, -RT, 0.f,  RT};
    const float tws[8] = {0.f, -RT, -1.f, -RT, 0.f,  RT, 1.f,  RT};
    const float SCALE = 0.01f / 158.39507568359375f;   // 0.01/sqrt(8*56*56)

    float contrib[8];
    #pragma unroll
    for (int k = 0; k < 8; ++k) {
        float re = 0.f, im = 0.f;
        #pragma unroll
        for (int l2 = 0; l2 < 8; ++l2) {
            int j = (l2 * k) & 7;
            re += twc[j]*fr[l2] - tws[j]*fi[l2];
            im += twc[j]*fi[l2] + tws[j]*fr[l2];
        }
        float mag = sqrtf(re*re + im*im);
        float xv  = x[(size_t)((b*Ln + k)*Cn + c) * HWn + p];
        contrib[k] = xv * (1.0f + SCALE * mag);
    }

    #pragma unroll
    for (int k = 0; k < 8; ++k)
        #pragma unroll
        for (int off = 16; off > 0; off >>= 1)
            contrib[k] += __shfl_down_sync(0xffffffff, contrib[k], off);

    __shared__ float ws[14][8];
    int wid = tid >> 5, lane = tid & 31;
    if (lane == 0) {
        #pragma unroll
        for (int k = 0; k < 8; ++k) ws[wid][k] = contrib[k];
    }
    __syncthreads();
    if (tid < 8) {
        float s = 0.f;
        #pragma unroll
        for (int w2 = 0; w2 < 14; ++w2) s += ws[w2][tid];
        g_ppart[(bc*7 + jb)*8 + tid] = s;
    }
}

// ============================================================================
// K3: pooled -> calibration scale s[b,l,ci] and dynamic bias fb[b,l,co].
// ============================================================================
__global__ __launch_bounds__(64) void k3_calib(
    const float* __restrict__ tw_, const float* __restrict__ tb,
    const float* __restrict__ fcw, const float* __restrict__ fcb,
    const float* __restrict__ convb)
{
    int bl = blockIdx.x;
    int b  = bl >> 3, l = bl & 7;
    int tid = threadIdx.x;

    __shared__ float pooled[64];
    __shared__ float fcp[65];

    float s = 0.f;
    #pragma unroll
    for (int j = 0; j < 7; ++j)
        s += g_ppart[((b*Cn + tid)*7 + j)*8 + l];
    float pv = s * (1.0f / 3136.0f);
    pooled[tid] = pv;
    fcp[tid] = fcw[tid] * pv;
    __syncthreads();

    float calib = tb[tid];
    #pragma unroll 8
    for (int c = 0; c < 64; ++c) calib += tw_[tid*64 + c] * pooled[c];
    g_s[bl*Cn + tid] = calib + 1.0f;

    if (tid == 0) {
        float f = fcb[0];
        for (int c = 0; c < 64; ++c) f += fcp[c];
        fcp[64] = f + 1.0f;
    }
    __syncthreads();
    g_fb[bl*Cn + tid] = convb[tid] * fcp[64];
}

// ============================================================================
// K4: conv3x3, s folded into weights; double-buffered x tile with register
// prefetch; packed f32x2 FMAs (weight pairs are natively packed in smem).
// grid = (16 co-groups, 64 bl), 448 threads; thread tile = 7 rows x 4 co.
// ============================================================================
__global__ __launch_bounds__(448, 2) void k4_conv(const float* __restrict__ x,
                                                  const float* __restrict__ convw) {
    __shared__ float xt[2*58*58];                   // 26.9 KB double buffer
    __shared__ __align__(16) float wsm[64*9*4];     // 9.2 KB: [ci][tap][cg]
    __shared__ float ssh[64];
    __shared__ float red[14*8];

    int cog = blockIdx.x;             // 0..15
    int bl  = blockIdx.y;             // 0..63
    int co0 = cog * 4;
    int tid = threadIdx.x;

    if (tid < 64) ssh[tid] = g_s[bl*Cn + tid];
    for (int e = tid; e < 2*58*58; e += 448) xt[e] = 0.0f;
    __syncthreads();

    for (int e = tid; e < 2304; e += 448) {
        int ci = e / 36; int r = e % 36; int tap = r >> 2; int cg = r & 3;
        wsm[e] = convw[((co0 + cg)*64 + ci)*9 + tap] * ssh[ci];
    }

    const float* xb = x + (size_t)bl * Cn * HWn;

    // preload ci = 0 into buffer 0
    #pragma unroll
    for (int k = 0; k < 7; ++k) {
        int e  = tid + k*448;
        int hh = e / 56, ww2 = e % 56;
        xt[(hh + 1)*58 + ww2 + 1] = __ldg(xb + e);
    }
    __syncthreads();

    int wc = tid % 56;
    int hq = tid / 56;                // 0..7
    int h0 = hq * 7;

    u64 acc2[7][2];
    #pragma unroll
    for (int r = 0; r < 7; ++r) { acc2[r][0] = 0ull; acc2[r][1] = 0ull; }

    for (int ci = 0; ci < 64; ++ci) {
        // issue next tile's global loads first (hidden behind the FMAs)
        float v[7];
        if (ci < 63) {
            const float* xp = xb + (size_t)(ci + 1) * HWn;
            #pragma unroll
            for (int k = 0; k < 7; ++k) v[k] = __ldg(xp + tid + k*448);
        }

        const float* xc = xt + (ci & 1) * (58*58);
        #pragma unroll
        for (int dc = 0; dc < 3; ++dc) {
            u64 a2[9];
            #pragma unroll
            for (int j = 0; j < 9; ++j) {
                float av = xc[(h0 + j)*58 + wc + dc];
                a2[j] = pack2(av, av);
            }
            #pragma unroll
            for (int dr = 0; dr < 3; ++dr) {
                const u64* wp = (const u64*)&wsm[(ci*9 + dr*3 + dc)*4];
                u64 w01 = wp[0];
                u64 w23 = wp[1];
                #pragma unroll
                for (int r = 0; r < 7; ++r) {
                    acc2[r][0] = ffma2(a2[r + dr], w01, acc2[r][0]);
                    acc2[r][1] = ffma2(a2[r + dr], w23, acc2[r][1]);
                }
            }
        }

        if (ci < 63) {
            float* xn = xt + ((ci + 1) & 1) * (58*58);
            #pragma unroll
            for (int k = 0; k < 7; ++k) {
                int e  = tid + k*448;
                int hh = e / 56, ww2 = e % 56;
                xn[(hh + 1)*58 + ww2 + 1] = v[k];
            }
        }
        __syncthreads();
    }

    // epilogue: + fb + residual, write y, accumulate BN partials
    float psum[4] = {0,0,0,0}, psq[4] = {0,0,0,0};
    #pragma unroll
    for (int cg = 0; cg < 4; ++cg) {
        int co = co0 + cg;
        float fbv = g_fb[bl*Cn + co];
        const float* xr = xb + (size_t)co * HWn;
        float* yp = g_y + (size_t)(bl*Cn + co) * HWn;
        #pragma unroll
        for (int r = 0; r < 7; ++r) {
            int pp = (h0 + r)*56 + wc;
            float2 pr = unpack2(acc2[r][cg >> 1]);
            float av = (cg & 1) ? pr.y : pr.x;
            float v = av + fbv + xr[pp];
            yp[pp] = v;
            psum[cg] += v;
            psq[cg]  += v*v;
        }
    }
    #pragma unroll
    for (int cg = 0; cg < 4; ++cg)
        #pragma unroll
        for (int off = 16; off > 0; off >>= 1) {
            psum[cg] += __shfl_down_sync(0xffffffff, psum[cg], off);
            psq[cg]  += __shfl_down_sync(0xffffffff, psq[cg],  off);
        }
    int wid = tid >> 5, lane = tid & 31;
    if (lane == 0) {
        #pragma unroll
        for (int cg = 0; cg < 4; ++cg) {
            red[wid*8 + cg]     = psum[cg];
            red[wid*8 + 4 + cg] = psq[cg];
        }
    }
    __syncthreads();
    if (tid < 8) {
        float s = 0.f;
        #pragma unroll
        for (int w2 = 0; w2 < 14; ++w2) s += red[w2*8 + tid];
        if (tid < 4) g_bnsum[(co0 + tid)*64 + bl]     = s;
        else         g_bnsq [(co0 + tid - 4)*64 + bl] = s;
    }
}

// ============================================================================
// K4b: final BN statistics (1 block, 64 threads; deterministic)
// ============================================================================
__global__ __launch_bounds__(64) void k4b_stats() {
    int c = threadIdx.x;
    float s = 0.f, q = 0.f;
    #pragma unroll 8
    for (int j = 0; j < 64; ++j) { s += g_bnsum[c*64 + j]; q += g_bnsq[c*64 + j]; }
    const float invN = 1.0f / (float)(BLn * HWn);
    float mean = s * invN;
    float var  = q * invN - mean*mean;
    g_mean[c]   = mean;
    g_invstd[c] = rsqrtf(var + 1e-5f);
}

// ============================================================================
// K5: BN normalize + affine + SiLU -> d_out (float4 vectorized)
// ============================================================================
__global__ __launch_bounds__(256) void k5_bnsilu(const float* __restrict__ gamma,
                                                 const float* __restrict__ beta,
                                                 float* __restrict__ out) {
    int i4 = blockIdx.x * 256 + threadIdx.x;
    int c = ((i4 * 4) / HWn) & 63;    // 3136 % 4 == 0 -> same c for all 4 lanes
    float4 y = ((const float4*)g_y)[i4];
    float m = g_mean[c], is = g_invstd[c] * gamma[c], bt = beta[c];
    float4 o;
    o.x = (y.x - m) * is + bt;
    o.y = (y.y - m) * is + bt;
    o.z = (y.z - m) * is + bt;
    o.w = (y.w - m) * is + bt;
    o.x = o.x / (1.0f + __expf(-o.x));
    o.y = o.y / (1.0f + __expf(-o.y));
    o.z = o.z / (1.0f + __expf(-o.z));
    o.w = o.w / (1.0f + __expf(-o.w));
    ((float4*)out)[i4] = o;
}

// ============================================================================
extern "C" void kernel_launch(void* const* d_in, const int* in_sizes, int n_in,
                              void* d_out, int out_size) {
    const float* x          = (const float*)d_in[0];
    const float* temporal_w = (const float*)d_in[1];
    const float* temporal_b = (const float*)d_in[2];
    const float* fc_w       = (const float*)d_in[3];
    const float* fc_b       = (const float*)d_in[4];
    const float* conv_w     = (const float*)d_in[5];
    const float* conv_b     = (const float*)d_in[6];
    const float* bn_gamma   = (const float*)d_in[7];
    const float* bn_beta    = (const float*)d_in[8];
    float* out = (float*)d_out;

    k1_dft2d<<<BCn*Ln, 224>>>(x);                 // 4096 blocks
    k2_ldft<<<BCn*7, 448>>>(x);                   // 3584 blocks
    k3_calib<<<BLn, 64>>>(temporal_w, temporal_b, fc_w, fc_b, conv_b);
    k4_conv<<<dim3(16, BLn), 448>>>(x, conv_w);   // 1024 blocks
    k4b_stats<<<1, 64>>>();
    k5_bnsilu<<<NTOT/1024, 256>>>(bn_gamma, bn_beta, out);
}

// round 4
// speedup vs baseline: 1.3955x; 1.0686x over previous
#include <cuda_runtime.h>
#include <math.h>

#define Bn 8
#define Ln 8
#define Cn 64
#define Hn 56
#define Wn 56
#define HWn 3136
#define BCn (Bn*Cn)        // 512
#define BLn (Bn*Ln)        // 64
#define NTOT (BLn*Cn*HWn)  // 12,845,056
#define KWC 29             // compact kw count (Hermitian half)
#define NPOS (56*KWC)      // 1624 positions per slab

typedef unsigned long long u64;

__device__ __forceinline__ u64 ffma2(u64 a, u64 b, u64 c) {
    u64 d;
    asm("fma.rn.f32x2 %0, %1, %2, %3;" : "=l"(d) : "l"(a), "l"(b), "l"(c));
    return d;
}
__device__ __forceinline__ u64 pack2(float lo, float hi) {
    u64 d;
    asm("mov.b64 %0, {%1, %2};" : "=l"(d) : "f"(lo), "f"(hi));
    return d;
}
__device__ __forceinline__ float2 unpack2(u64 v) {
    float2 r;
    asm("mov.b64 {%0, %1}, %2;" : "=f"(r.x), "=f"(r.y) : "l"(v));
    return r;
}

// ---------------- scratch (device globals; no runtime allocation) ----------
__device__ float2 g_F2[BCn*Ln*NPOS];    // compact 2D-DFT (kw<=28) ~53MB
__device__ float  g_y[NTOT];            // pre-BN conv output (~51MB)
__device__ float  g_ppart[BCn*4*Ln];    // pooled partials (deterministic reduce)
__device__ float  g_s[BLn*Cn];          // per (b,l,ci) input-channel scale
__device__ float  g_fb[BLn*Cn];         // per (b,l,co) dynamic bias
__device__ float  g_bnsum[Cn*BLn];
__device__ float  g_bnsq[Cn*BLn];
__device__ float  g_mean[Cn];
__device__ float  g_invstd[Cn];

// ============================================================================
// K1: 2D DFT per (b,c,l) slab; TWO slabs per block (threads 0-111 / 112-223,
// pure pointer split, no divergence). Hermitian: compute kw in [0,31], store
// only kw<=28 compactly (stride 29). f32x2 complex MACs throughout.
// Dynamic smem: 86016 B.
// ============================================================================
__global__ __launch_bounds__(224) void k1_dft2d(const float* __restrict__ x) {
    extern __shared__ char k1sm[];
    u64*   t1a = (u64*)k1sm;              // [2][56*33] (re,im)
    u64*   t1s = t1a + 2*56*33;           // [2][56*33] (im,re)
    u64*   twp = t1s + 2*56*33;           // 56  (c,s)
    u64*   twA = twp + 56;                // 56  (c,c)
    u64*   twB = twA + 56;                // 56  (-s,s)
    float* xs  = (float*)(twB + 56);      // [2][56*57]

    int bid = blockIdx.x;                 // bc*4 + lpair
    int bc  = bid >> 2;
    int lp  = bid & 3;
    int b   = bc >> 6;
    int c   = bc & 63;
    int tid = threadIdx.x;
    int s   = (tid >= 112) ? 1 : 0;
    int loc = tid - s*112;                // 0..111
    int l   = lp*2 + s;

    float* xss = xs  + s*(56*57);
    u64*   t1A = t1a + s*(56*33);
    u64*   t1S = t1s + s*(56*33);

    const float* xp = x + (size_t)((b*Ln + l)*Cn + c) * HWn;
    #pragma unroll
    for (int k = 0; k < 28; ++k) {
        int e = loc + k*112;
        xss[(e/56)*57 + (e%56)] = xp[e];
    }
    if (tid < 56) {
        float sv, cv;
        sincosf(-6.28318530717958647692f * (float)tid / 56.0f, &sv, &cv);
        twp[tid] = pack2(cv, sv);
        twA[tid] = pack2(cv, cv);
        twB[tid] = pack2(-sv, sv);
    }
    __syncthreads();

    int th = loc >> 3;                    // 0..13
    int tk = loc & 7;                     // 0..7
    int h0  = th * 4;
    int kw0 = tk * 4;                     // kw in [0,32)

    // ---- Stage B: W-DFT (real input) for kw in [0,32)
    {
        u64 acc2[4][4];
        #pragma unroll
        for (int i = 0; i < 4; ++i)
            #pragma unroll
            for (int j = 0; j < 4; ++j) acc2[i][j] = 0ull;
        int idx[4] = {0, 0, 0, 0};
        for (int w = 0; w < 56; ++w) {
            u64 xa2[4];
            #pragma unroll
            for (int i = 0; i < 4; ++i) {
                float v = xss[(h0 + i)*57 + w];
                xa2[i] = pack2(v, v);
            }
            #pragma unroll
            for (int j = 0; j < 4; ++j) {
                u64 t = twp[idx[j]];
                #pragma unroll
                for (int i = 0; i < 4; ++i)
                    acc2[i][j] = ffma2(xa2[i], t, acc2[i][j]);
                idx[j] += kw0 + j;
                if (idx[j] >= 56) idx[j] -= 56;
            }
        }
        #pragma unroll
        for (int i = 0; i < 4; ++i)
            #pragma unroll
            for (int j = 0; j < 4; ++j) {
                int o = (h0 + i)*33 + kw0 + j;
                t1A[o] = acc2[i][j];
                float2 v = unpack2(acc2[i][j]);
                t1S[o] = pack2(v.y, v.x);
            }
    }
    __syncthreads();

    // ---- Stage C: H-DFT (complex), write compact kw<=28 only
    {
        u64 acc2[4][4];
        #pragma unroll
        for (int i = 0; i < 4; ++i)
            #pragma unroll
            for (int j = 0; j < 4; ++j) acc2[i][j] = 0ull;
        int idx[4] = {0, 0, 0, 0};        // (h*kh_i)%56, kh_i = h0+i
        for (int h = 0; h < 56; ++h) {
            u64 tA[4], tB[4];
            #pragma unroll
            for (int i = 0; i < 4; ++i) {
                tA[i] = twA[idx[i]];
                tB[i] = twB[idx[i]];
                idx[i] += h0 + i;
                if (idx[i] >= 56) idx[i] -= 56;
            }
            u64 ua[4], us[4];
            #pragma unroll
            for (int j = 0; j < 4; ++j) {
                ua[j] = t1A[h*33 + kw0 + j];
                us[j] = t1S[h*33 + kw0 + j];
            }
            #pragma unroll
            for (int i = 0; i < 4; ++i)
                #pragma unroll
                for (int j = 0; j < 4; ++j) {
                    acc2[i][j] = ffma2(tA[i], ua[j], acc2[i][j]);
                    acc2[i][j] = ffma2(tB[i], us[j], acc2[i][j]);
                }
        }
        float2* outp = g_F2 + (size_t)(bc*Ln + l) * NPOS;
        #pragma unroll
        for (int i = 0; i < 4; ++i) {
            int kh = h0 + i;
            #pragma unroll
            for (int j = 0; j < 4; ++j) {
                int kw = kw0 + j;
                if (kw <= 28) {
                    float2 v = unpack2(acc2[i][j]);
                    outp[kh*KWC + kw] = v;
                }
            }
        }
    }
}

// ============================================================================
// K2: 8-point DFT along L + magnitude at compact positions (kw<=28); mirror
// positions reuse the same magnitudes with k -> (8-k)&7. Pooled partials.
// grid = (BC*4), 448 threads; position idx = jb*448+tid (valid < 1624).
// ============================================================================
__global__ __launch_bounds__(448) void k2_ldft(const float* __restrict__ x) {
    int bx = blockIdx.x;
    int bc = bx >> 2, jb = bx & 3;
    int b  = bc >> 6, c = bc & 63;
    int tid = threadIdx.x;
    int idx = jb * 448 + tid;             // 0..1791

    float contrib[8];
    #pragma unroll
    for (int k = 0; k < 8; ++k) contrib[k] = 0.f;

    if (idx < NPOS) {
        int kh = idx / KWC, kw = idx % KWC;
        int p  = kh*56 + kw;
        int pm = ((56 - kh) % 56)*56 + ((56 - kw) % 56);
        bool do_m = (kw >= 1 && kw <= 27);

        const float2* f2 = g_F2 + (size_t)(bc*Ln) * NPOS + idx;
        float fr[8], fi[8];
        #pragma unroll
        for (int l2 = 0; l2 < 8; ++l2) {
            float2 v = f2[(size_t)l2 * NPOS];
            fr[l2] = v.x; fi[l2] = v.y;
        }

        const float RT = 0.70710678118654752f;
        const float twc[8] = {1.f,  RT, 0.f, -RT, -1.f, -RT, 0.f,  RT};
        const float tws[8] = {0.f, -RT, -1.f, -RT, 0.f,  RT, 1.f,  RT};
        const float SCALE = 0.01f / 158.39507568359375f;   // 0.01/sqrt(8*56*56)

        float mag[8];
        #pragma unroll
        for (int k = 0; k < 8; ++k) {
            float re = 0.f, im = 0.f;
            #pragma unroll
            for (int l2 = 0; l2 < 8; ++l2) {
                int j = (l2 * k) & 7;
                re += twc[j]*fr[l2] - tws[j]*fi[l2];
                im += twc[j]*fi[l2] + tws[j]*fr[l2];
            }
            mag[k] = sqrtf(re*re + im*im);
        }

        #pragma unroll
        for (int k = 0; k < 8; ++k) {
            const float* xl = x + (size_t)((b*Ln + k)*Cn + c) * HWn;
            float v = xl[p] * (1.0f + SCALE * mag[k]);
            if (do_m)
                v += xl[pm] * (1.0f + SCALE * mag[(8 - k) & 7]);
            contrib[k] = v;
        }
    }

    #pragma unroll
    for (int k = 0; k < 8; ++k)
        #pragma unroll
        for (int off = 16; off > 0; off >>= 1)
            contrib[k] += __shfl_down_sync(0xffffffff, contrib[k], off);

    __shared__ float ws[14][8];
    int wid = tid >> 5, lane = tid & 31;
    if (lane == 0) {
        #pragma unroll
        for (int k = 0; k < 8; ++k) ws[wid][k] = contrib[k];
    }
    __syncthreads();
    if (tid < 8) {
        float s = 0.f;
        #pragma unroll
        for (int w2 = 0; w2 < 14; ++w2) s += ws[w2][tid];
        g_ppart[(bc*4 + jb)*8 + tid] = s;
    }
}

// ============================================================================
// K3: pooled -> calibration scale s[b,l,ci] and dynamic bias fb[b,l,co].
// ============================================================================
__global__ __launch_bounds__(64) void k3_calib(
    const float* __restrict__ tw_, const float* __restrict__ tb,
    const float* __restrict__ fcw, const float* __restrict__ fcb,
    const float* __restrict__ convb)
{
    int bl = blockIdx.x;
    int b  = bl >> 3, l = bl & 7;
    int tid = threadIdx.x;

    __shared__ float pooled[64];
    __shared__ float fcp[65];

    float s = 0.f;
    #pragma unroll
    for (int j = 0; j < 4; ++j)
        s += g_ppart[((b*Cn + tid)*4 + j)*8 + l];
    float pv = s * (1.0f / 3136.0f);
    pooled[tid] = pv;
    fcp[tid] = fcw[tid] * pv;
    __syncthreads();

    float calib = tb[tid];
    #pragma unroll 8
    for (int c = 0; c < 64; ++c) calib += tw_[tid*64 + c] * pooled[c];
    g_s[bl*Cn + tid] = calib + 1.0f;

    if (tid == 0) {
        float f = fcb[0];
        for (int c = 0; c < 64; ++c) f += fcp[c];
        fcp[64] = f + 1.0f;
    }
    __syncthreads();
    g_fb[bl*Cn + tid] = convb[tid] * fcp[64];
}

// ============================================================================
// K4: conv3x3, s folded into weights; double-buffered x tile with register
// prefetch; packed f32x2 FMAs (weight pairs natively packed in smem).
// ============================================================================
__global__ __launch_bounds__(448, 2) void k4_conv(const float* __restrict__ x,
                                                  const float* __restrict__ convw) {
    __shared__ float xt[2*58*58];                   // 26.9 KB double buffer
    __shared__ __align__(16) float wsm[64*9*4];     // 9.2 KB: [ci][tap][cg]
    __shared__ float ssh[64];
    __shared__ float red[14*8];

    int cog = blockIdx.x;             // 0..15
    int bl  = blockIdx.y;             // 0..63
    int co0 = cog * 4;
    int tid = threadIdx.x;

    if (tid < 64) ssh[tid] = g_s[bl*Cn + tid];
    for (int e = tid; e < 2*58*58; e += 448) xt[e] = 0.0f;
    __syncthreads();

    for (int e = tid; e < 2304; e += 448) {
        int ci = e / 36; int r = e % 36; int tap = r >> 2; int cg = r & 3;
        wsm[e] = convw[((co0 + cg)*64 + ci)*9 + tap] * ssh[ci];
    }

    const float* xb = x + (size_t)bl * Cn * HWn;

    #pragma unroll
    for (int k = 0; k < 7; ++k) {
        int e  = tid + k*448;
        int hh = e / 56, ww2 = e % 56;
        xt[(hh + 1)*58 + ww2 + 1] = __ldg(xb + e);
    }
    __syncthreads();

    int wc = tid % 56;
    int hq = tid / 56;                // 0..7
    int h0 = hq * 7;

    u64 acc2[7][2];
    #pragma unroll
    for (int r = 0; r < 7; ++r) { acc2[r][0] = 0ull; acc2[r][1] = 0ull; }

    for (int ci = 0; ci < 64; ++ci) {
        float v[7];
        if (ci < 63) {
            const float* xp = xb + (size_t)(ci + 1) * HWn;
            #pragma unroll
            for (int k = 0; k < 7; ++k) v[k] = __ldg(xp + tid + k*448);
        }

        const float* xc = xt + (ci & 1) * (58*58);
        #pragma unroll
        for (int dc = 0; dc < 3; ++dc) {
            u64 a2[9];
            #pragma unroll
            for (int j = 0; j < 9; ++j) {
                float av = xc[(h0 + j)*58 + wc + dc];
                a2[j] = pack2(av, av);
            }
            #pragma unroll
            for (int dr = 0; dr < 3; ++dr) {
                const u64* wp = (const u64*)&wsm[(ci*9 + dr*3 + dc)*4];
                u64 w01 = wp[0];
                u64 w23 = wp[1];
                #pragma unroll
                for (int r = 0; r < 7; ++r) {
                    acc2[r][0] = ffma2(a2[r + dr], w01, acc2[r][0]);
                    acc2[r][1] = ffma2(a2[r + dr], w23, acc2[r][1]);
                }
            }
        }

        if (ci < 63) {
            float* xn = xt + ((ci + 1) & 1) * (58*58);
            #pragma unroll
            for (int k = 0; k < 7; ++k) {
                int e  = tid + k*448;
                int hh = e / 56, ww2 = e % 56;
                xn[(hh + 1)*58 + ww2 + 1] = v[k];
            }
        }
        __syncthreads();
    }

    float psum[4] = {0,0,0,0}, psq[4] = {0,0,0,0};
    #pragma unroll
    for (int cg = 0; cg < 4; ++cg) {
        int co = co0 + cg;
        float fbv = g_fb[bl*Cn + co];
        const float* xr = xb + (size_t)co * HWn;
        float* yp = g_y + (size_t)(bl*Cn + co) * HWn;
        #pragma unroll
        for (int r = 0; r < 7; ++r) {
            int pp = (h0 + r)*56 + wc;
            float2 pr = unpack2(acc2[r][cg >> 1]);
            float av = (cg & 1) ? pr.y : pr.x;
            float v = av + fbv + xr[pp];
            yp[pp] = v;
            psum[cg] += v;
            psq[cg]  += v*v;
        }
    }
    #pragma unroll
    for (int cg = 0; cg < 4; ++cg)
        #pragma unroll
        for (int off = 16; off > 0; off >>= 1) {
            psum[cg] += __shfl_down_sync(0xffffffff, psum[cg], off);
            psq[cg]  += __shfl_down_sync(0xffffffff, psq[cg],  off);
        }
    int wid = tid >> 5, lane = tid & 31;
    if (lane == 0) {
        #pragma unroll
        for (int cg = 0; cg < 4; ++cg) {
            red[wid*8 + cg]     = psum[cg];
            red[wid*8 + 4 + cg] = psq[cg];
        }
    }
    __syncthreads();
    if (tid < 8) {
        float s = 0.f;
        #pragma unroll
        for (int w2 = 0; w2 < 14; ++w2) s += red[w2*8 + tid];
        if (tid < 4) g_bnsum[(co0 + tid)*64 + bl]     = s;
        else         g_bnsq [(co0 + tid - 4)*64 + bl] = s;
    }
}

// ============================================================================
// K4b: final BN statistics (1 block, 64 threads; deterministic)
// ============================================================================
__global__ __launch_bounds__(64) void k4b_stats() {
    int c = threadIdx.x;
    float s = 0.f, q = 0.f;
    #pragma unroll 8
    for (int j = 0; j < 64; ++j) { s += g_bnsum[c*64 + j]; q += g_bnsq[c*64 + j]; }
    const float invN = 1.0f / (float)(BLn * HWn);
    float mean = s * invN;
    float var  = q * invN - mean*mean;
    g_mean[c]   = mean;
    g_invstd[c] = rsqrtf(var + 1e-5f);
}

// ============================================================================
// K5: BN normalize + affine + SiLU -> d_out (float4 vectorized)
// ============================================================================
__global__ __launch_bounds__(256) void k5_bnsilu(const float* __restrict__ gamma,
                                                 const float* __restrict__ beta,
                                                 float* __restrict__ out) {
    int i4 = blockIdx.x * 256 + threadIdx.x;
    int c = ((i4 * 4) / HWn) & 63;    // 3136 % 4 == 0 -> same c for all 4 lanes
    float4 y = ((const float4*)g_y)[i4];
    float m = g_mean[c], is = g_invstd[c] * gamma[c], bt = beta[c];
    float4 o;
    o.x = (y.x - m) * is + bt;
    o.y = (y.y - m) * is + bt;
    o.z = (y.z - m) * is + bt;
    o.w = (y.w - m) * is + bt;
    o.x = o.x / (1.0f + __expf(-o.x));
    o.y = o.y / (1.0f + __expf(-o.y));
    o.z = o.z / (1.0f + __expf(-o.z));
    o.w = o.w / (1.0f + __expf(-o.w));
    ((float4*)out)[i4] = o;
}

// ============================================================================
extern "C" void kernel_launch(void* const* d_in, const int* in_sizes, int n_in,
                              void* d_out, int out_size) {
    const float* x          = (const float*)d_in[0];
    const float* temporal_w = (const float*)d_in[1];
    const float* temporal_b = (const float*)d_in[2];
    const float* fc_w       = (const float*)d_in[3];
    const float* fc_b       = (const float*)d_in[4];
    const float* conv_w     = (const float*)d_in[5];
    const float* conv_b     = (const float*)d_in[6];
    const float* bn_gamma   = (const float*)d_in[7];
    const float* bn_beta    = (const float*)d_in[8];
    float* out = (float*)d_out;

    const int K1_SMEM = (2*56*33*2)*8 + 3*56*8 + (2*56*57)*4;   // 86016 B
    static int configured = 0;
    if (!configured) {
        cudaFuncSetAttribute(k1_dft2d, cudaFuncAttributeMaxDynamicSharedMemorySize, K1_SMEM);
        configured = 1;
    }

    k1_dft2d<<<BCn*Ln/2, 224, K1_SMEM>>>(x);      // 2048 blocks, 2 slabs each
    k2_ldft<<<BCn*4, 448>>>(x);                   // 2048 blocks
    k3_calib<<<BLn, 64>>>(temporal_w, temporal_b, fc_w, fc_b, conv_b);
    k4_conv<<<dim3(16, BLn), 448>>>(x, conv_w);   // 1024 blocks
    k4b_stats<<<1, 64>>>();
    k5_bnsilu<<<NTOT/1024, 256>>>(bn_gamma, bn_beta, out);
}